// round 1
// baseline (speedup 1.0000x reference)
#include <cuda_runtime.h>
#include <math.h>
#include <stdint.h>

#define C_CH 256
#define POOL 7
#define FEAT (POOL*POOL*C_CH)      /* 12544 */
#define R_MAX 1024
#define DCLS_MAX 80
#define M_MAX (R_MAX*DCLS_MAX)     /* 81920 */
#define NIMG_MAX 4
#define LOG_MAX_CONST 4.1351665567423556f

/* ------------------ scratch (static device globals, no allocation) ------------------ */
__device__ float  g_x0[(size_t)R_MAX*FEAT];     /* pooled features, 51.4 MB */
__device__ float  g_x1[(size_t)R_MAX*1024];
__device__ float  g_x2[(size_t)R_MAX*1024];
__device__ float  g_logits[(size_t)R_MAX*96];
__device__ float  g_reg[(size_t)R_MAX*4*96];
__device__ float  g_cscore[M_MAX];
__device__ float4 g_cbox[M_MAX];
__device__ float  g_score_c[(size_t)NIMG_MAX*M_MAX];
__device__ float4 g_box_c[(size_t)NIMG_MAX*M_MAX];
__device__ float  g_area_c[(size_t)NIMG_MAX*M_MAX];
__device__ int    g_cls_c[(size_t)NIMG_MAX*M_MAX];
__device__ int    g_cnt[NIMG_MAX];

/* ------------------ ROI align: one block per proposal, 256 threads = channels ------- */
__global__ void roi_align_kernel(const float* __restrict__ prop,
                                 const int*   __restrict__ imidx,
                                 const float* __restrict__ f0, const float* __restrict__ f1,
                                 const float* __restrict__ f2, const float* __restrict__ f3,
                                 int H0, int H1, int H2, int H3)
{
    int r = blockIdx.x;
    __shared__ int   s_lvl, s_img, s_H;
    __shared__ int   s_y0[49], s_y1[49], s_x0[49], s_x1[49];
    __shared__ float s_wx[49], s_wy[49];

    if (threadIdx.x == 0) {
        float x1 = prop[r*4+0], y1 = prop[r*4+1], x2 = prop[r*4+2], y2 = prop[r*4+3];
        float pw = x2 - x1, ph = y2 - y1;
        float l = floorf(4.0f + log2f(sqrtf(pw*ph) / 224.0f + 1e-6f));
        l = fminf(fmaxf(l, 2.0f), 5.0f);
        int lvl = (int)l - 2;
        s_lvl = lvl;
        s_img = imidx[r];
        s_H   = (lvl==0 ? H0 : lvl==1 ? H1 : lvl==2 ? H2 : H3);
    }
    __syncthreads();
    int lvl = s_lvl, H = s_H;

    if (threadIdx.x < 49) {
        int py = threadIdx.x / 7, px = threadIdx.x % 7;
        float s  = 1.0f / (float)(4 << lvl);
        float x1 = prop[r*4+0]*s, y1 = prop[r*4+1]*s;
        float x2 = prop[r*4+2]*s, y2 = prop[r*4+3]*s;
        float gx = (px + 0.5f) / (float)POOL;
        float gy = (py + 0.5f) / (float)POOL;
        float xx = x1 + gx*(x2 - x1) - 0.5f;
        float yy = y1 + gy*(y2 - y1) - 0.5f;
        float x0f = floorf(xx), y0f = floorf(yy);
        s_wx[threadIdx.x] = xx - x0f;
        s_wy[threadIdx.x] = yy - y0f;
        int xi = (int)x0f, yi = (int)y0f;
        s_x0[threadIdx.x] = min(max(xi,     0), H-1);
        s_x1[threadIdx.x] = min(max(xi + 1, 0), H-1);
        s_y0[threadIdx.x] = min(max(yi,     0), H-1);
        s_y1[threadIdx.x] = min(max(yi + 1, 0), H-1);
    }
    __syncthreads();

    const float* fm = (lvl==0 ? f0 : lvl==1 ? f1 : lvl==2 ? f2 : f3);
    size_t imgBase = (size_t)s_img * H * H * C_CH;
    int c = threadIdx.x;
    float* out = &g_x0[(size_t)r * FEAT];

    for (int b = 0; b < 49; b++) {
        float wx = s_wx[b], wy = s_wy[b];
        size_t row0 = imgBase + (size_t)s_y0[b] * H * C_CH;
        size_t row1 = imgBase + (size_t)s_y1[b] * H * C_CH;
        size_t cx0  = (size_t)s_x0[b] * C_CH + c;
        size_t cx1  = (size_t)s_x1[b] * C_CH + c;
        float v00 = fm[row0 + cx0];
        float v01 = fm[row0 + cx1];
        float v10 = fm[row1 + cx0];
        float v11 = fm[row1 + cx1];
        float v = v00*(1.f-wx)*(1.f-wy) + v01*wx*(1.f-wy)
                + v10*(1.f-wx)*wy       + v11*wx*wy;
        out[b*C_CH + c] = v;
    }
}

/* ------------------ SGEMM: C = A(MxK) * B(KxN) + bias, optional ReLU ---------------- */
/* 128x64 block tile, BK=32, 128 threads, 8x8 microtile. Requires K % 32 == 0.          */
#define BM 128
#define BN 64
#define BKT 32
__global__ __launch_bounds__(128) void sgemm_bias(const float* __restrict__ A,
                                                  const float* __restrict__ B,
                                                  const float* __restrict__ bias,
                                                  float* __restrict__ Cm,
                                                  int M, int N, int K, int relu)
{
    __shared__ float As[BKT][BM + 4];   /* +4 keeps 16B alignment for float4 LDS */
    __shared__ float Bs[BKT][BN];

    int tid = threadIdx.x;
    int tx = tid % 8;        /* column group: cols tx*8 .. +7 */
    int ty = tid / 8;        /* row group:    rows ty*8 .. +7 */
    int mBase = blockIdx.y * BM, nBase = blockIdx.x * BN;

    float acc[8][8];
    #pragma unroll
    for (int i = 0; i < 8; i++)
        #pragma unroll
        for (int j = 0; j < 8; j++) acc[i][j] = 0.f;

    int aRow = tid / 8;          /* 0..15 */
    int aK   = (tid % 8) * 4;    /* 0..28 */
    int bK   = tid / 16;         /* 0..7  */
    int bN   = (tid % 16) * 4;   /* 0..60 */

    for (int kt = 0; kt < K; kt += BKT) {
        #pragma unroll
        for (int p = 0; p < 8; p++) {
            int row = mBase + p*16 + aRow;
            float4 v = make_float4(0.f,0.f,0.f,0.f);
            if (row < M) v = *(const float4*)&A[(size_t)row*K + kt + aK];
            As[aK+0][p*16+aRow] = v.x;
            As[aK+1][p*16+aRow] = v.y;
            As[aK+2][p*16+aRow] = v.z;
            As[aK+3][p*16+aRow] = v.w;
        }
        #pragma unroll
        for (int p = 0; p < 4; p++) {
            int kk = kt + p*8 + bK;
            const float* brow = B + (size_t)kk*N + nBase + bN;
            float4 v;
            v.x = (nBase+bN+0 < N) ? brow[0] : 0.f;
            v.y = (nBase+bN+1 < N) ? brow[1] : 0.f;
            v.z = (nBase+bN+2 < N) ? brow[2] : 0.f;
            v.w = (nBase+bN+3 < N) ? brow[3] : 0.f;
            *(float4*)&Bs[p*8+bK][bN] = v;
        }
        __syncthreads();

        #pragma unroll
        for (int k = 0; k < BKT; k++) {
            float a[8], b[8];
            *(float4*)&a[0] = *(const float4*)&As[k][ty*8];
            *(float4*)&a[4] = *(const float4*)&As[k][ty*8+4];
            *(float4*)&b[0] = *(const float4*)&Bs[k][tx*8];
            *(float4*)&b[4] = *(const float4*)&Bs[k][tx*8+4];
            #pragma unroll
            for (int i = 0; i < 8; i++)
                #pragma unroll
                for (int j = 0; j < 8; j++)
                    acc[i][j] += a[i]*b[j];
        }
        __syncthreads();
    }

    #pragma unroll
    for (int i = 0; i < 8; i++) {
        int row = mBase + ty*8 + i;
        if (row >= M) continue;
        #pragma unroll
        for (int j = 0; j < 8; j++) {
            int col = nBase + tx*8 + j;
            if (col >= N) continue;
            float v = acc[i][j] + bias[col];
            if (relu) v = fmaxf(v, 0.f);
            Cm[(size_t)row*N + col] = v;
        }
    }
}

/* ------------------ softmax + box decode: one block (128 thr) per proposal ---------- */
__global__ void decode_kernel(const float* __restrict__ prop,
                              const int*   __restrict__ imidx,
                              const float* __restrict__ imsizes,
                              const float* __restrict__ sthr_p,
                              const float* __restrict__ minsz_p,
                              int NC)
{
    int r = blockIdx.x;
    int t = threadIdx.x;
    __shared__ float sl[128];
    __shared__ float smax, ssum;

    if (t < NC) sl[t] = g_logits[(size_t)r*NC + t];
    __syncthreads();
    if (t == 0) { float m = sl[0]; for (int i = 1; i < NC; i++) m = fmaxf(m, sl[i]); smax = m; }
    __syncthreads();
    if (t < NC) sl[t] = expf(sl[t] - smax);
    __syncthreads();
    if (t == 0) { float s = 0.f; for (int i = 0; i < NC; i++) s += sl[i]; ssum = s; }
    __syncthreads();

    int D = NC - 1;
    if (t < D) {
        float score = sl[t+1] / ssum;
        float px1 = prop[r*4+0], py1 = prop[r*4+1];
        float px2 = prop[r*4+2], py2 = prop[r*4+3];
        float pw = px2 - px1, ph = py2 - py1;
        float cx = (px1 + px2)*0.5f, cy = (py1 + py2)*0.5f;
        const float* rg = &g_reg[(size_t)r*(NC*4) + (t+1)*4];
        float dx = rg[0]*0.1f, dy = rg[1]*0.1f;
        float dw = fminf(rg[2]*0.2f, LOG_MAX_CONST);
        float dh = fminf(rg[3]*0.2f, LOG_MAX_CONST);
        float ncx = dx*pw + cx, ncy = dy*ph + cy;
        float nw  = expf(dw)*pw, nh  = expf(dh)*ph;
        int im = imidx[r];
        float hb = imsizes[im*2+0], wb = imsizes[im*2+1];
        float bx1 = fminf(fmaxf(ncx - nw*0.5f, 0.f), wb);
        float bx2 = fminf(fmaxf(ncx + nw*0.5f, 0.f), wb);
        float by1 = fminf(fmaxf(ncy - nh*0.5f, 0.f), hb);
        float by2 = fminf(fmaxf(ncy + nh*0.5f, 0.f), hb);
        float sthr = *sthr_p, minsz = *minsz_p;
        bool valid = (score > sthr) && (bx2 - bx1 >= minsz) && (by2 - by1 >= minsz);
        int m = r*D + t;
        g_cscore[m] = valid ? score : -1.0f;
        g_cbox[m]   = make_float4(bx1, by1, bx2, by2);
    }
}

/* ------------------ deterministic (order-preserving) per-image compaction ----------- */
__global__ void compact_kernel(const int* __restrict__ imidx, int M, int D)
{
    int img  = blockIdx.x;
    int tid  = threadIdx.x;
    int lane = tid & 31, wid = tid >> 5;
    __shared__ int warpSum[32], warpOff[32];
    __shared__ int sBase, sTot;
    if (tid == 0) sBase = 0;
    __syncthreads();

    for (int start = 0; start < M; start += 1024) {
        int m = start + tid;
        bool f = false; float sc = 0.f;
        if (m < M) { sc = g_cscore[m]; f = (sc > 0.f) && (imidx[m / D] == img); }
        unsigned ball = __ballot_sync(0xffffffffu, f);
        int pre = __popc(ball & ((1u << lane) - 1u));
        if (lane == 0) warpSum[wid] = __popc(ball);
        __syncthreads();
        if (tid == 0) {
            int s = 0;
            for (int w = 0; w < 32; w++) { warpOff[w] = s; s += warpSum[w]; }
            sTot = s;
        }
        __syncthreads();
        if (f) {
            int k = sBase + warpOff[wid] + pre;
            size_t o = (size_t)img*M_MAX + k;
            float4 b = g_cbox[m];
            g_score_c[o] = sc;
            g_box_c[o]   = b;
            g_area_c[o]  = (b.z - b.x)*(b.w - b.y);
            g_cls_c[o]   = (m % D) + 1;
        }
        __syncthreads();
        if (tid == 0) sBase += sTot;
        __syncthreads();
    }
    if (tid == 0) g_cnt[img] = sBase;
}

/* ------------------ sequential NMS: one block per image ---------------------------- */
__global__ __launch_bounds__(1024) void nms_kernel(const float* __restrict__ iou_p,
                                                   float* __restrict__ out,
                                                   int n, int imtop)
{
    int img = blockIdx.x;
    int tid = threadIdx.x;
    int K = g_cnt[img];
    float iouT = *iou_p;
    float*  sc = &g_score_c[(size_t)img*M_MAX];
    float4* bx = &g_box_c[(size_t)img*M_MAX];
    float*  ar = &g_area_c[(size_t)img*M_MAX];
    int*    cl = &g_cls_c[(size_t)img*M_MAX];

    __shared__ float sval[1024];
    __shared__ int   sidx[1024];
    __shared__ float4 shb;  __shared__ float sha;  __shared__ int shc;

    float* oB = out + (size_t)img*imtop*4;
    float* oS = out + (size_t)n*imtop*4 + (size_t)img*imtop;
    float* oC = out + (size_t)n*imtop*5 + (size_t)img*imtop;

    for (int t = 0; t < imtop; t++) {
        /* argmax with first-index tie-break (matches jnp.argmax) */
        float best = -1e30f; int bi = 0x7fffffff;
        for (int k = tid; k < K; k += blockDim.x) {
            float v = sc[k];
            if (v > best || (v == best && k < bi)) { best = v; bi = k; }
        }
        sval[tid] = best; sidx[tid] = bi;
        __syncthreads();
        for (int s = blockDim.x >> 1; s > 0; s >>= 1) {
            if (tid < s) {
                float ov = sval[tid+s]; int oi = sidx[tid+s];
                if (ov > sval[tid] || (ov == sval[tid] && oi < sidx[tid])) {
                    sval[tid] = ov; sidx[tid] = oi;
                }
            }
            __syncthreads();
        }
        float wv = sval[0]; int wi = sidx[0];
        if (tid == 0 && wv > 0.f) { shb = bx[wi]; sha = ar[wi]; shc = cl[wi]; }
        __syncthreads();

        if (wv > 0.f) {
            float4 wb = shb; float wa = sha; int wc = shc;
            for (int k = tid; k < K; k += blockDim.x) {
                if (k == wi) { sc[k] = -1.f; continue; }
                if (cl[k] != wc) continue;  /* class-offset boxes never overlap cross-class */
                float4 b = bx[k];
                float iw = fmaxf(fminf(wb.z, b.z) - fmaxf(wb.x, b.x), 0.f);
                float ih = fmaxf(fminf(wb.w, b.w) - fmaxf(wb.y, b.y), 0.f);
                float inter = iw * ih;
                float iou = inter / (wa + ar[k] - inter + 1e-6f);
                if (iou > iouT) sc[k] = -1.f;
            }
            if (tid == 0) {
                oB[t*4+0] = wb.x; oB[t*4+1] = wb.y; oB[t*4+2] = wb.z; oB[t*4+3] = wb.w;
                oS[t] = wv;
                oC[t] = (float)wc;
            }
        } else {
            if (tid == 0) {
                oB[t*4+0] = 0.f; oB[t*4+1] = 0.f; oB[t*4+2] = 0.f; oB[t*4+3] = 0.f;
                oS[t] = 0.f;
                oC[t] = -1.f;
            }
        }
        __syncthreads();
    }
}

/* ------------------ host launch ---------------------------------------------------- */
extern "C" void kernel_launch(void* const* d_in, const int* in_sizes, int n_in,
                              void* d_out, int out_size)
{
    const float* prop    = (const float*)d_in[0];
    const int*   imidx   = (const int*)  d_in[1];
    const float* f0      = (const float*)d_in[2];
    const float* f1      = (const float*)d_in[3];
    const float* f2      = (const float*)d_in[4];
    const float* f3      = (const float*)d_in[5];
    const float* W0      = (const float*)d_in[6];
    const float* b0      = (const float*)d_in[7];
    const float* W1      = (const float*)d_in[8];
    const float* b1      = (const float*)d_in[9];
    const float* Wc      = (const float*)d_in[10];
    const float* bc      = (const float*)d_in[11];
    const float* Wr      = (const float*)d_in[12];
    const float* br      = (const float*)d_in[13];
    const float* imsizes = (const float*)d_in[14];
    const float* sthr    = (const float*)d_in[15];
    const float* iouthr  = (const float*)d_in[16];
    /* d_in[17] = imtop (derived from out_size instead) */
    const float* minsz   = (const float*)d_in[18];

    int R  = in_sizes[0] / 4;
    int n  = in_sizes[14] / 2;
    int imtop = out_size / (6 * n);
    int N0 = in_sizes[7];    /* 1024 */
    int N1 = in_sizes[9];    /* 1024 */
    int NC = in_sizes[11];   /* 81  */
    int NR = in_sizes[13];   /* 324 */
    int D  = NC - 1;
    int M  = R * D;

    int H0 = (int)(sqrt((double)in_sizes[2] / ((double)n * C_CH)) + 0.5);
    int H1 = (int)(sqrt((double)in_sizes[3] / ((double)n * C_CH)) + 0.5);
    int H2 = (int)(sqrt((double)in_sizes[4] / ((double)n * C_CH)) + 0.5);
    int H3 = (int)(sqrt((double)in_sizes[5] / ((double)n * C_CH)) + 0.5);

    float *px0, *px1, *px2, *plog, *preg;
    cudaGetSymbolAddress((void**)&px0,  g_x0);
    cudaGetSymbolAddress((void**)&px1,  g_x1);
    cudaGetSymbolAddress((void**)&px2,  g_x2);
    cudaGetSymbolAddress((void**)&plog, g_logits);
    cudaGetSymbolAddress((void**)&preg, g_reg);

    /* 1. ROI align -> pooled features */
    roi_align_kernel<<<R, 256>>>(prop, imidx, f0, f1, f2, f3, H0, H1, H2, H3);

    /* 2. FC1 (FEAT->N0) + ReLU */
    {
        dim3 g((N0 + BN - 1)/BN, (R + BM - 1)/BM);
        sgemm_bias<<<g, 128>>>(px0, W0, b0, px1, R, N0, FEAT, 1);
    }
    /* 3. FC2 (N0->N1) + ReLU */
    {
        dim3 g((N1 + BN - 1)/BN, (R + BM - 1)/BM);
        sgemm_bias<<<g, 128>>>(px1, W1, b1, px2, R, N1, N0, 1);
    }
    /* 4. class head logits (N1->NC) */
    {
        dim3 g((NC + BN - 1)/BN, (R + BM - 1)/BM);
        sgemm_bias<<<g, 128>>>(px2, Wc, bc, plog, R, NC, N1, 0);
    }
    /* 5. reg head (N1->NR) */
    {
        dim3 g((NR + BN - 1)/BN, (R + BM - 1)/BM);
        sgemm_bias<<<g, 128>>>(px2, Wr, br, preg, R, NR, N1, 0);
    }
    /* 6. softmax + box decode */
    decode_kernel<<<R, 128>>>(prop, imidx, imsizes, sthr, minsz, NC);

    /* 7. deterministic per-image compaction */
    compact_kernel<<<n, 1024>>>(imidx, M, D);

    /* 8. sequential NMS + output write */
    nms_kernel<<<n, 1024>>>(iouthr, (float*)d_out, n, imtop);
}